// round 12
// baseline (speedup 1.0000x reference)
#include <cuda_runtime.h>

#define NMAX 100000
#define EMAX 600000
#define HID 128
#define NG 256
#define BN_EPS 1e-5f
#define FULLMASK 0xffffffffu

typedef unsigned long long ull;
typedef unsigned int uint;

// ---------------- scratch (device globals; no allocs allowed) ----------------
__device__ int   g_rowstart[NMAX + 1];  // CSR row offsets (by dst)
__device__ int   g_fill[NMAX];          // fill cursor
__device__ int   g_csr[EMAX];           // src indices grouped by dst
__device__ int   g_bsum[256];           // scan block sums
__device__ float g_dinv[NMAX];
__device__ float g_xs[NMAX * 8];        // x * dinv, padded to 8 floats
__device__ float g_h[NMAX * HID];       // layer activations (fp32)
__device__ unsigned short g_hls[NMAX * HID];  // (h@W)*dinv in bf16 (gather source)
__device__ float g_sums[NG * HID];
__device__ float g_cnts[NG];

// ---------------- f32x2 / bf16 helpers (sm_103a) ----------------
__device__ __forceinline__ ull pk2(float x, float y) {
    ull r;
    asm("mov.b64 %0, {%1, %2};" : "=l"(r) : "f"(x), "f"(y));
    return r;
}
__device__ __forceinline__ void upk2(ull v, float& x, float& y) {
    asm("mov.b64 {%0, %1}, %2;" : "=f"(x), "=f"(y) : "l"(v));
}
__device__ __forceinline__ ull ffma2(ull a, ull b, ull c) {
    ull r;
    asm("fma.rn.f32x2 %0, %1, %2, %3;" : "=l"(r) : "l"(a), "l"(b), "l"(c));
    return r;
}
__device__ __forceinline__ ull fadd2(ull a, ull b) {
    ull r;
    asm("add.rn.f32x2 %0, %1, %2;" : "=l"(r) : "l"(a), "l"(b));
    return r;
}
// pack two f32 into bf16x2: lo -> low half, hi -> high half
__device__ __forceinline__ uint bfpack(float lo, float hi) {
    uint r;
    asm("cvt.rn.bf16x2.f32 %0, %1, %2;" : "=r"(r) : "f"(hi), "f"(lo));
    return r;
}
// unpack bf16x2 (u32) into packed f32x2 pair (exact: bf16 -> f32 is <<16)
__device__ __forceinline__ ull bf2f2(uint u) {
    uint lo = u << 16;
    uint hi = u & 0xffff0000u;
    ull r;
    asm("mov.b64 %0, {%1, %2};" : "=l"(r) : "r"(lo), "r"(hi));
    return r;
}

// ---------------- CSR build ----------------
__global__ void k_zero_rs(int L) {
    int i = blockIdx.x * blockDim.x + threadIdx.x;
    if (i < L) g_rowstart[i] = 0;
}

__global__ void k_hist(const int* __restrict__ dst, int e) {
    int i = blockIdx.x * blockDim.x + threadIdx.x;
    if (i < e) atomicAdd(&g_rowstart[dst[i] + 1], 1);
}

// phase 1: per-block (1024 elems) inclusive scan, in place; block total -> g_bsum
// Fused extras: emits dinv (pre-scan value at idx i+1 = degree of node i),
// writes g_xs = x * dinv (padded to 8), zeros pooling buffers.
__global__ void k_scan1(const float* __restrict__ x, int L, int n) {
    __shared__ int wsum[8];
    __shared__ int woff[8];
    int t = threadIdx.x;
    int base = blockIdx.x * 1024;
    int i0 = base + t * 4;
    int v[4];
#pragma unroll
    for (int j = 0; j < 4; j++) {
        int idx = i0 + j;
        v[j] = (idx < L) ? g_rowstart[idx] : 0;
        if (idx >= 1 && idx <= n) {
            int node = idx - 1;
            float dv = rsqrtf((float)v[j] + 1.f);
            g_dinv[node] = dv;
            float xv[8];
#pragma unroll
            for (int k = 0; k < 7; k++) xv[k] = __ldg(x + node * 7 + k) * dv;
            xv[7] = 0.f;
            float4* dst4 = (float4*)(g_xs + (size_t)node * 8);
            dst4[0] = make_float4(xv[0], xv[1], xv[2], xv[3]);
            dst4[1] = make_float4(xv[4], xv[5], xv[6], xv[7]);
        }
    }
    int gid = blockIdx.x * blockDim.x + t;
    int stride = gridDim.x * blockDim.x;
    for (int z = gid; z < NG * HID; z += stride) g_sums[z] = 0.f;
    if (gid < NG) g_cnts[gid] = 0.f;

    v[1] += v[0]; v[2] += v[1]; v[3] += v[2];
    int tsum = v[3];
    int lane = t & 31, w = t >> 5;
    int xsc = tsum;
#pragma unroll
    for (int o = 1; o < 32; o <<= 1) {
        int y = __shfl_up_sync(FULLMASK, xsc, o);
        if (lane >= o) xsc += y;
    }
    if (lane == 31) wsum[w] = xsc;
    __syncthreads();
    if (t == 0) {
        int s = 0;
        for (int k = 0; k < 8; k++) { woff[k] = s; s += wsum[k]; }
        g_bsum[blockIdx.x] = s;
    }
    __syncthreads();
    int ex = woff[w] + xsc - tsum;
#pragma unroll
    for (int j = 0; j < 4; j++)
        if (i0 + j < L) g_rowstart[i0 + j] = ex + v[j];
}

// phase 2: single block exclusive scan of block sums (nb <= 128)
__global__ void k_scan2(int nb) {
    __shared__ int wsum[4];
    __shared__ int woff[4];
    int t = threadIdx.x;
    int v = (t < nb) ? g_bsum[t] : 0;
    int lane = t & 31, w = t >> 5;
    int x = v;
#pragma unroll
    for (int o = 1; o < 32; o <<= 1) {
        int y = __shfl_up_sync(FULLMASK, x, o);
        if (lane >= o) x += y;
    }
    if (lane == 31) wsum[w] = x;
    __syncthreads();
    if (t == 0) {
        int s = 0;
        for (int k = 0; k < 4; k++) { woff[k] = s; s += wsum[k]; }
    }
    __syncthreads();
    if (t < nb) g_bsum[t] = woff[w] + x - v;
}

// phase 3: add block offsets; seed g_fill with row starts
__global__ void k_scan3(int L, int n) {
    int t = threadIdx.x;
    int base = blockIdx.x * 1024;
    int off = g_bsum[blockIdx.x];
    int i0 = base + t * 4;
#pragma unroll
    for (int j = 0; j < 4; j++) {
        int idx = i0 + j;
        if (idx < L) {
            int val = g_rowstart[idx] + off;
            g_rowstart[idx] = val;
            if (idx < n) g_fill[idx] = val;
        }
    }
}

__global__ void k_fill(const int* __restrict__ src, const int* __restrict__ dst, int e) {
    int i = blockIdx.x * blockDim.x + threadIdx.x;
    if (i < e) {
        int pos = atomicAdd(&g_fill[dst[i]], 1);
        g_csr[pos] = src[i];
    }
}

// ---- layer 0 fused: aggregate xs (8-dim) -> GEMM 8x128 -> BN -> ReLU -> g_h ----
__global__ void k_layer0(const float* __restrict__ W0, const float* __restrict__ b0,
                         const float* __restrict__ gamma, const float* __restrict__ beta,
                         const float* __restrict__ mean, const float* __restrict__ var,
                         int n) {
    __shared__ float sW[8 * 128];   // row 7 zero-padded
    for (int i = threadIdx.x; i < 8 * 128; i += blockDim.x)
        sW[i] = (i < 7 * 128) ? W0[i] : 0.f;
    __syncthreads();

    int warp = (blockIdx.x * blockDim.x + threadIdx.x) >> 5;
    int lane = threadIdx.x & 31;
    if (warp >= n) return;

    int s0 = g_rowstart[warp];
    int s1 = g_rowstart[warp + 1];
    float dv = g_dinv[warp];
    int half = lane & 1;
    int sub = lane >> 1;

    float4 acc = make_float4(0.f, 0.f, 0.f, 0.f);
    for (int j0 = s0; j0 < s1; j0 += 32) {
        int myidx = (j0 + lane < s1) ? __ldg(&g_csr[j0 + lane]) : 0;
        int m = min(32, s1 - j0);
#pragma unroll
        for (int base = 0; base < 32; base += 16) {
            if (base >= m) break;
            int e = base + sub;
            int s = __shfl_sync(FULLMASK, myidx, e);
            if (e < m) {
                float4 v = __ldg((const float4*)(g_xs + (size_t)s * 8) + half);
                acc.x += v.x; acc.y += v.y; acc.z += v.z; acc.w += v.w;
            }
        }
    }
#pragma unroll
    for (int off = 2; off < 32; off <<= 1) {
        acc.x += __shfl_down_sync(FULLMASK, acc.x, off);
        acc.y += __shfl_down_sync(FULLMASK, acc.y, off);
        acc.z += __shfl_down_sync(FULLMASK, acc.z, off);
        acc.w += __shfl_down_sync(FULLMASK, acc.w, off);
    }
    if (lane < 2) {
        float4 self = __ldg((const float4*)(g_xs + (size_t)warp * 8) + lane);
        acc.x = (acc.x + self.x) * dv;
        acc.y = (acc.y + self.y) * dv;
        acc.z = (acc.z + self.z) * dv;
        acc.w = (acc.w + self.w) * dv;
    }
    float xa[8];
    xa[0] = __shfl_sync(FULLMASK, acc.x, 0);
    xa[1] = __shfl_sync(FULLMASK, acc.y, 0);
    xa[2] = __shfl_sync(FULLMASK, acc.z, 0);
    xa[3] = __shfl_sync(FULLMASK, acc.w, 0);
    xa[4] = __shfl_sync(FULLMASK, acc.x, 1);
    xa[5] = __shfl_sync(FULLMASK, acc.y, 1);
    xa[6] = __shfl_sync(FULLMASK, acc.z, 1);
    xa[7] = __shfl_sync(FULLMASK, acc.w, 1);

    float4 r = make_float4(0.f, 0.f, 0.f, 0.f);
#pragma unroll
    for (int k = 0; k < 8; k++) {
        float4 w = ((const float4*)(sW + k * 128))[lane];
        r.x += xa[k] * w.x; r.y += xa[k] * w.y;
        r.z += xa[k] * w.z; r.w += xa[k] * w.w;
    }
    float4 gm = __ldg((const float4*)gamma + lane);
    float4 vr = __ldg((const float4*)var + lane);
    float4 bi = __ldg((const float4*)b0 + lane);
    float4 mn = __ldg((const float4*)mean + lane);
    float4 bt = __ldg((const float4*)beta + lane);
    float rv[4] = {r.x, r.y, r.z, r.w};
    float gmv[4] = {gm.x, gm.y, gm.z, gm.w};
    float vrv[4] = {vr.x, vr.y, vr.z, vr.w};
    float biv[4] = {bi.x, bi.y, bi.z, bi.w};
    float mnv[4] = {mn.x, mn.y, mn.z, mn.w};
    float btv[4] = {bt.x, bt.y, bt.z, bt.w};
    float out[4];
#pragma unroll
    for (int j = 0; j < 4; j++) {
        float scale = gmv[j] * rsqrtf(vrv[j] + BN_EPS);
        float v = rv[j] + biv[j];
        v = (v - mnv[j]) * scale + btv[j];
        out[j] = fmaxf(v, 0.f);
    }
    ((float4*)(g_h + (size_t)warp * HID))[lane] =
        make_float4(out[0], out[1], out[2], out[3]);
}

// ---- 128x128 GEMM: g_h @ W, scaled by dinv, f32x2; bf16 output to g_hls ----
__global__ __launch_bounds__(256, 2) void k_gemm128(const float* __restrict__ W, int n) {
    __shared__ float sW[32][128];
    __shared__ float sA[32][132];   // 16B-aligned rows for LDS.128

    const float* __restrict__ A = g_h;

    int row0 = blockIdx.x * 128;
    int tid = threadIdx.x;
    int lane = tid & 31, warp = tid >> 5;

    ull acc2[8][4];
#pragma unroll
    for (int p = 0; p < 8; p++)
#pragma unroll
        for (int j = 0; j < 4; j++) acc2[p][j] = 0ull;

    for (int kt = 0; kt < 128; kt += 32) {
        const float4* Wv = (const float4*)(W + kt * 128);
        float4* sWv = (float4*)(&sW[0][0]);
#pragma unroll
        for (int i = 0; i < 4; i++) sWv[tid + 256 * i] = Wv[tid + 256 * i];
#pragma unroll
        for (int i = 0; i < 4; i++) {
            int idx = tid + 256 * i;
            int r = idx >> 3, c = idx & 7;
            int row = row0 + r;
            float4 v = make_float4(0.f, 0.f, 0.f, 0.f);
            if (row < n) v = ((const float4*)(A + (size_t)row * 128 + kt))[c];
            sA[c * 4 + 0][r] = v.x; sA[c * 4 + 1][r] = v.y;
            sA[c * 4 + 2][r] = v.z; sA[c * 4 + 3][r] = v.w;
        }
        __syncthreads();
#pragma unroll 8
        for (int k = 0; k < 32; k++) {
            float4 b = ((const float4*)(&sW[k][0]))[lane];
            ull bb0 = pk2(b.x, b.x), bb1 = pk2(b.y, b.y);
            ull bb2 = pk2(b.z, b.z), bb3 = pk2(b.w, b.w);
            const ull* ap = (const ull*)(&sA[k][warp * 16]);
#pragma unroll
            for (int p = 0; p < 8; p++) {
                ull a = ap[p];
                acc2[p][0] = ffma2(a, bb0, acc2[p][0]);
                acc2[p][1] = ffma2(a, bb1, acc2[p][1]);
                acc2[p][2] = ffma2(a, bb2, acc2[p][2]);
                acc2[p][3] = ffma2(a, bb3, acc2[p][3]);
            }
        }
        __syncthreads();
    }
#pragma unroll
    for (int p = 0; p < 8; p++) {
        float lo[4], hi[4];
#pragma unroll
        for (int j = 0; j < 4; j++) upk2(acc2[p][j], lo[j], hi[j]);
        int r0 = row0 + warp * 16 + 2 * p;
        int r1 = r0 + 1;
        if (r0 < n) {
            float dv = g_dinv[r0];
            uint p0 = bfpack(lo[0] * dv, lo[1] * dv);
            uint p1 = bfpack(lo[2] * dv, lo[3] * dv);
            ((uint2*)(g_hls + (size_t)r0 * HID))[lane] = make_uint2(p0, p1);
        }
        if (r1 < n) {
            float dv = g_dinv[r1];
            uint p0 = bfpack(hi[0] * dv, hi[1] * dv);
            uint p1 = bfpack(hi[2] * dv, hi[3] * dv);
            ((uint2*)(g_hls + (size_t)r1 * HID))[lane] = make_uint2(p0, p1);
        }
    }
}

// ------- fused gather-aggregate + BN + ReLU; half-warp edge pairs -------
// one warp per dst node; lanes 0-15 process even edges, 16-31 odd edges.
// each lane loads uint4 (8 bf16 columns); cross-half merge via shfl_xor 16.
__global__ void k_aggregate(const float* __restrict__ b, const float* __restrict__ gamma,
                            const float* __restrict__ beta, const float* __restrict__ mean,
                            const float* __restrict__ var, int n) {
    int warp = (blockIdx.x * blockDim.x + threadIdx.x) >> 5;
    int lane = threadIdx.x & 31;
    if (warp >= n) return;

    int sub = lane >> 4;      // 0: even edges, 1: odd edges
    int c = lane & 15;        // uint4 column group (8 bf16 columns)

    int s0 = g_rowstart[warp];
    int s1 = g_rowstart[warp + 1];

    ull a0 = 0, a1 = 0, a2 = 0, a3 = 0;
    // self term: low half only (both halves cover same columns)
    if (sub == 0) {
        uint4 sv = __ldg((const uint4*)(g_hls + (size_t)warp * HID) + c);
        a0 = bf2f2(sv.x); a1 = bf2f2(sv.y); a2 = bf2f2(sv.z); a3 = bf2f2(sv.w);
    }

    for (int j0 = s0; j0 < s1; j0 += 32) {
        int myidx = (j0 + lane < s1) ? __ldg(&g_csr[j0 + lane]) : 0;
        int m = min(32, s1 - j0);
        int j = 0;
        for (; j + 16 <= m; j += 16) {     // 8 edge-pairs = 16 edges
            int ia[8];
#pragma unroll
            for (int q = 0; q < 8; q++)
                ia[q] = __shfl_sync(FULLMASK, myidx, j + q * 2 + sub);
            uint4 v[8];
#pragma unroll
            for (int q = 0; q < 8; q++)
                v[q] = __ldg((const uint4*)(g_hls + (size_t)ia[q] * HID) + c);
#pragma unroll
            for (int q = 0; q < 8; q++) {
                a0 = fadd2(a0, bf2f2(v[q].x));
                a1 = fadd2(a1, bf2f2(v[q].y));
                a2 = fadd2(a2, bf2f2(v[q].z));
                a3 = fadd2(a3, bf2f2(v[q].w));
            }
        }
        for (; j + 2 <= m; j += 2) {       // one edge-pair
            int ii = __shfl_sync(FULLMASK, myidx, j + sub);
            uint4 v = __ldg((const uint4*)(g_hls + (size_t)ii * HID) + c);
            a0 = fadd2(a0, bf2f2(v.x));
            a1 = fadd2(a1, bf2f2(v.y));
            a2 = fadd2(a2, bf2f2(v.z));
            a3 = fadd2(a3, bf2f2(v.w));
        }
        if (j < m) {                       // odd tail: low half only
            int ii = __shfl_sync(FULLMASK, myidx, j);
            if (sub == 0) {
                uint4 v = __ldg((const uint4*)(g_hls + (size_t)ii * HID) + c);
                a0 = fadd2(a0, bf2f2(v.x));
                a1 = fadd2(a1, bf2f2(v.y));
                a2 = fadd2(a2, bf2f2(v.z));
                a3 = fadd2(a3, bf2f2(v.w));
            }
        }
    }

    // merge halves (cols identical across halves)
    a0 = fadd2(a0, __shfl_xor_sync(FULLMASK, a0, 16));
    a1 = fadd2(a1, __shfl_xor_sync(FULLMASK, a1, 16));
    a2 = fadd2(a2, __shfl_xor_sync(FULLMASK, a2, 16));
    a3 = fadd2(a3, __shfl_xor_sync(FULLMASK, a3, 16));

    if (sub == 0) {
        float av[8];
        upk2(a0, av[0], av[1]); upk2(a1, av[2], av[3]);
        upk2(a2, av[4], av[5]); upk2(a3, av[6], av[7]);
        float dv = g_dinv[warp];
        float4 gm0 = __ldg((const float4*)gamma + 2 * c);
        float4 gm1 = __ldg((const float4*)gamma + 2 * c + 1);
        float4 vr0 = __ldg((const float4*)var + 2 * c);
        float4 vr1 = __ldg((const float4*)var + 2 * c + 1);
        float4 bi0 = __ldg((const float4*)b + 2 * c);
        float4 bi1 = __ldg((const float4*)b + 2 * c + 1);
        float4 mn0 = __ldg((const float4*)mean + 2 * c);
        float4 mn1 = __ldg((const float4*)mean + 2 * c + 1);
        float4 bt0 = __ldg((const float4*)beta + 2 * c);
        float4 bt1 = __ldg((const float4*)beta + 2 * c + 1);
        float gmv[8] = {gm0.x, gm0.y, gm0.z, gm0.w, gm1.x, gm1.y, gm1.z, gm1.w};
        float vrv[8] = {vr0.x, vr0.y, vr0.z, vr0.w, vr1.x, vr1.y, vr1.z, vr1.w};
        float biv[8] = {bi0.x, bi0.y, bi0.z, bi0.w, bi1.x, bi1.y, bi1.z, bi1.w};
        float mnv[8] = {mn0.x, mn0.y, mn0.z, mn0.w, mn1.x, mn1.y, mn1.z, mn1.w};
        float btv[8] = {bt0.x, bt0.y, bt0.z, bt0.w, bt1.x, bt1.y, bt1.z, bt1.w};
        float out[8];
#pragma unroll
        for (int j = 0; j < 8; j++) {
            float scale = gmv[j] * rsqrtf(vrv[j] + BN_EPS);
            float v = av[j] * dv + biv[j];
            v = (v - mnv[j]) * scale + btv[j];
            out[j] = fmaxf(v, 0.f);
        }
        float4* dst4 = (float4*)(g_h + (size_t)warp * HID) + 2 * c;
        dst4[0] = make_float4(out[0], out[1], out[2], out[3]);
        dst4[1] = make_float4(out[4], out[5], out[6], out[7]);
    }
}

// ---------------- pooling (128 nodes per block) ----------------
__global__ void k_pool(const int* __restrict__ batch, int n) {
    int start = blockIdx.x * 128;
    int end = min(n, start + 128);
    if (start >= n) return;
    int t = threadIdx.x;          // feature column, 128 threads
    int cur = batch[start];
    float acc = 0.f, cnt = 0.f;
    for (int node = start; node < end; node++) {
        int g = batch[node];
        if (g != cur) {
            atomicAdd(&g_sums[cur * HID + t], acc);
            if (t == 0) atomicAdd(&g_cnts[cur], cnt);
            acc = 0.f; cnt = 0.f; cur = g;
        }
        acc += g_h[(size_t)node * HID + t];
        cnt += 1.f;
    }
    atomicAdd(&g_sums[cur * HID + t], acc);
    if (t == 0) atomicAdd(&g_cnts[cur], cnt);
}

// ------- classifier (pocket MLP fused): per-graph block, 192 -> 96 -> 1 -------
__global__ void k_classify(const float* __restrict__ pocket,
                           const float* __restrict__ pw1, const float* __restrict__ pb1,
                           const float* __restrict__ pw2, const float* __restrict__ pb2,
                           const float* __restrict__ cw1, const float* __restrict__ cb1,
                           const float* __restrict__ cw2, const float* __restrict__ cb2,
                           float* __restrict__ out) {
    __shared__ float p1[64];
    __shared__ float emb[192];
    __shared__ float hid[96];
    int g = blockIdx.x;
    int t = threadIdx.x;  // 192 threads
    if (t < 64) {
        float a = pb1[t];
        for (int k = 0; k < 28; k++) a += pocket[k] * pw1[k * 64 + t];
        p1[t] = fmaxf(a, 0.f);
    }
    if (t < 128) {
        float cnt = fmaxf(g_cnts[g], 1.f);
        emb[t] = g_sums[g * HID + t] / cnt;
    }
    __syncthreads();
    if (t >= 128) {
        int c = t - 128;
        float b = pb2[c];
        for (int k = 0; k < 64; k++) b += p1[k] * pw2[k * 64 + c];
        emb[t] = b;
    }
    __syncthreads();
    if (t < 96) {
        float a = cb1[t];
#pragma unroll 4
        for (int c = 0; c < 192; c++) a += emb[c] * cw1[c * 96 + t];
        hid[t] = fmaxf(a, 0.f);
    }
    __syncthreads();
    if (t == 0) {
        float o = cb2[0];
        for (int j = 0; j < 96; j++) o += hid[j] * cw2[j];
        out[g] = o;
    }
}

// ---------------- launch ----------------
extern "C" void kernel_launch(void* const* d_in, const int* in_sizes, int n_in,
                              void* d_out, int out_size) {
    const float* x      = (const float*)d_in[0];
    const int*   ei     = (const int*)  d_in[1];
    const int*   batch  = (const int*)  d_in[2];
    const float* pocket = (const float*)d_in[3];
    const float* W0 = (const float*)d_in[4];
    const float* b0 = (const float*)d_in[5];
    const float* W1 = (const float*)d_in[6];
    const float* b1 = (const float*)d_in[7];
    const float* W2 = (const float*)d_in[8];
    const float* b2 = (const float*)d_in[9];
    const float* bn_gamma = (const float*)d_in[10];
    const float* bn_beta  = (const float*)d_in[11];
    const float* bn_mean  = (const float*)d_in[12];
    const float* bn_var   = (const float*)d_in[13];
    const float* pw1 = (const float*)d_in[14];
    const float* pb1 = (const float*)d_in[15];
    const float* pw2 = (const float*)d_in[16];
    const float* pb2 = (const float*)d_in[17];
    const float* cw1 = (const float*)d_in[18];
    const float* cb1 = (const float*)d_in[19];
    const float* cw2 = (const float*)d_in[20];
    const float* cb2 = (const float*)d_in[21];
    float* out = (float*)d_out;

    int n = in_sizes[0] / 7;       // 100000
    int e = in_sizes[1] / 2;       // 600000
    const int* src = ei;
    const int* dst = ei + e;

    int L = n + 1;
    int NB = (L + 1023) / 1024;    // 98

    // CSR build (by dst); scan1 fuses dinv + xs-prep + pool-zero
    k_zero_rs<<<(L + 255) / 256, 256>>>(L);
    k_hist<<<(e + 255) / 256, 256>>>(dst, e);
    k_scan1<<<NB, 256>>>(x, L, n);
    k_scan2<<<1, 128>>>(NB);
    k_scan3<<<NB, 256>>>(L, n);
    k_fill<<<(e + 255) / 256, 256>>>(src, dst, e);

    int agg_blocks = (n * 32 + 255) / 256;

    // layer 0: fused aggregate(8-dim) + GEMM + BN + ReLU
    k_layer0<<<agg_blocks, 256>>>(W0, b0, bn_gamma, bn_beta, bn_mean, bn_var, n);
    // layer 1
    k_gemm128<<<(n + 127) / 128, 256>>>(W1, n);
    k_aggregate<<<agg_blocks, 256>>>(b1, bn_gamma + HID, bn_beta + HID,
                                     bn_mean + HID, bn_var + HID, n);
    // layer 2
    k_gemm128<<<(n + 127) / 128, 256>>>(W2, n);
    k_aggregate<<<agg_blocks, 256>>>(b2, bn_gamma + 2 * HID, bn_beta + 2 * HID,
                                     bn_mean + 2 * HID, bn_var + 2 * HID, n);

    // pooling + classifier (pocket fused)
    k_pool<<<(n + 127) / 128, 128>>>(batch, n);
    k_classify<<<NG, 192>>>(pocket, pw1, pb1, pw2, pb2,
                            cw1, cb1, cw2, cb2, out);
}

// round 13
// speedup vs baseline: 1.0764x; 1.0764x over previous
#include <cuda_runtime.h>

#define NMAX 100000
#define EMAX 600000
#define HID 128
#define NG 256
#define BN_EPS 1e-5f
#define FULLMASK 0xffffffffu

typedef unsigned long long ull;
typedef unsigned int uint;

// ---------------- scratch (device globals; no allocs allowed) ----------------
__device__ int   g_rowstart[NMAX + 1];  // CSR row offsets (by dst)
__device__ int   g_fill[NMAX];          // fill cursor
__device__ int   g_csr[EMAX];           // src indices grouped by dst
__device__ int   g_bsum[256];           // scan block sums
__device__ float g_dinv[NMAX];
__device__ float g_xs[NMAX * 8];        // x * dinv, padded to 8 floats
__device__ float g_h[NMAX * HID];       // layer activations (fp32)
__device__ unsigned short g_hls[NMAX * HID];  // (h@W)*dinv in bf16 (gather source)
__device__ float g_sums[NG * HID];
__device__ float g_cnts[NG];

// ---------------- f32x2 / bf16 helpers (sm_103a) ----------------
__device__ __forceinline__ ull pk2(float x, float y) {
    ull r;
    asm("mov.b64 %0, {%1, %2};" : "=l"(r) : "f"(x), "f"(y));
    return r;
}
__device__ __forceinline__ void upk2(ull v, float& x, float& y) {
    asm("mov.b64 {%0, %1}, %2;" : "=f"(x), "=f"(y) : "l"(v));
}
__device__ __forceinline__ ull ffma2(ull a, ull b, ull c) {
    ull r;
    asm("fma.rn.f32x2 %0, %1, %2, %3;" : "=l"(r) : "l"(a), "l"(b), "l"(c));
    return r;
}
__device__ __forceinline__ ull fadd2(ull a, ull b) {
    ull r;
    asm("add.rn.f32x2 %0, %1, %2;" : "=l"(r) : "l"(a), "l"(b));
    return r;
}
// pack two f32 into bf16x2: lo -> low half, hi -> high half
__device__ __forceinline__ uint bfpack(float lo, float hi) {
    uint r;
    asm("cvt.rn.bf16x2.f32 %0, %1, %2;" : "=r"(r) : "f"(hi), "f"(lo));
    return r;
}
// unpack bf16x2 (u32) into packed f32x2 pair (exact: bf16 -> f32 is <<16)
__device__ __forceinline__ ull bf2f2(uint u) {
    uint lo = u << 16;
    uint hi = u & 0xffff0000u;
    ull r;
    asm("mov.b64 %0, {%1, %2};" : "=l"(r) : "r"(lo), "r"(hi));
    return r;
}

// ---------------- CSR build ----------------
__global__ void k_zero_rs(int L) {
    int i = blockIdx.x * blockDim.x + threadIdx.x;
    if (i < L) g_rowstart[i] = 0;
}

__global__ void k_hist(const int* __restrict__ dst, int e) {
    int i = blockIdx.x * blockDim.x + threadIdx.x;
    if (i < e) atomicAdd(&g_rowstart[dst[i] + 1], 1);
}

// phase 1: per-block (1024 elems) inclusive scan, in place; block total -> g_bsum
// Fused extras: emits dinv (pre-scan value at idx i+1 = degree of node i),
// writes g_xs = x * dinv (padded to 8), zeros pooling buffers.
__global__ void k_scan1(const float* __restrict__ x, int L, int n) {
    __shared__ int wsum[8];
    __shared__ int woff[8];
    int t = threadIdx.x;
    int base = blockIdx.x * 1024;
    int i0 = base + t * 4;
    int v[4];
#pragma unroll
    for (int j = 0; j < 4; j++) {
        int idx = i0 + j;
        v[j] = (idx < L) ? g_rowstart[idx] : 0;
        if (idx >= 1 && idx <= n) {
            int node = idx - 1;
            float dv = rsqrtf((float)v[j] + 1.f);
            g_dinv[node] = dv;
            float xv[8];
#pragma unroll
            for (int k = 0; k < 7; k++) xv[k] = __ldg(x + node * 7 + k) * dv;
            xv[7] = 0.f;
            float4* dst4 = (float4*)(g_xs + (size_t)node * 8);
            dst4[0] = make_float4(xv[0], xv[1], xv[2], xv[3]);
            dst4[1] = make_float4(xv[4], xv[5], xv[6], xv[7]);
        }
    }
    int gid = blockIdx.x * blockDim.x + t;
    int stride = gridDim.x * blockDim.x;
    for (int z = gid; z < NG * HID; z += stride) g_sums[z] = 0.f;
    if (gid < NG) g_cnts[gid] = 0.f;

    v[1] += v[0]; v[2] += v[1]; v[3] += v[2];
    int tsum = v[3];
    int lane = t & 31, w = t >> 5;
    int xsc = tsum;
#pragma unroll
    for (int o = 1; o < 32; o <<= 1) {
        int y = __shfl_up_sync(FULLMASK, xsc, o);
        if (lane >= o) xsc += y;
    }
    if (lane == 31) wsum[w] = xsc;
    __syncthreads();
    if (t == 0) {
        int s = 0;
        for (int k = 0; k < 8; k++) { woff[k] = s; s += wsum[k]; }
        g_bsum[blockIdx.x] = s;
    }
    __syncthreads();
    int ex = woff[w] + xsc - tsum;
#pragma unroll
    for (int j = 0; j < 4; j++)
        if (i0 + j < L) g_rowstart[i0 + j] = ex + v[j];
}

// phase 2: single block exclusive scan of block sums (nb <= 128)
__global__ void k_scan2(int nb) {
    __shared__ int wsum[4];
    __shared__ int woff[4];
    int t = threadIdx.x;
    int v = (t < nb) ? g_bsum[t] : 0;
    int lane = t & 31, w = t >> 5;
    int x = v;
#pragma unroll
    for (int o = 1; o < 32; o <<= 1) {
        int y = __shfl_up_sync(FULLMASK, x, o);
        if (lane >= o) x += y;
    }
    if (lane == 31) wsum[w] = x;
    __syncthreads();
    if (t == 0) {
        int s = 0;
        for (int k = 0; k < 4; k++) { woff[k] = s; s += wsum[k]; }
    }
    __syncthreads();
    if (t < nb) g_bsum[t] = woff[w] + x - v;
}

// phase 3: add block offsets; seed g_fill; also count nodes per graph
__global__ void k_scan3(const int* __restrict__ batch, int L, int n) {
    int t = threadIdx.x;
    int base = blockIdx.x * 1024;
    int off = g_bsum[blockIdx.x];
    int i0 = base + t * 4;
#pragma unroll
    for (int j = 0; j < 4; j++) {
        int idx = i0 + j;
        if (idx < L) {
            int val = g_rowstart[idx] + off;
            g_rowstart[idx] = val;
            if (idx < n) {
                g_fill[idx] = val;
                atomicAdd(&g_cnts[__ldg(batch + idx)], 1.f);
            }
        }
    }
}

__global__ void k_fill(const int* __restrict__ src, const int* __restrict__ dst, int e) {
    int i = blockIdx.x * blockDim.x + threadIdx.x;
    if (i < e) {
        int pos = atomicAdd(&g_fill[dst[i]], 1);
        g_csr[pos] = src[i];
    }
}

// ---- layer 0 fused: aggregate xs (8-dim) -> GEMM 8x128 -> BN -> ReLU -> g_h ----
__global__ void k_layer0(const float* __restrict__ W0, const float* __restrict__ b0,
                         const float* __restrict__ gamma, const float* __restrict__ beta,
                         const float* __restrict__ mean, const float* __restrict__ var,
                         int n) {
    __shared__ float sW[8 * 128];   // row 7 zero-padded
    for (int i = threadIdx.x; i < 8 * 128; i += blockDim.x)
        sW[i] = (i < 7 * 128) ? W0[i] : 0.f;
    __syncthreads();

    int warp = (blockIdx.x * blockDim.x + threadIdx.x) >> 5;
    int lane = threadIdx.x & 31;
    if (warp >= n) return;

    int s0 = g_rowstart[warp];
    int s1 = g_rowstart[warp + 1];
    float dv = g_dinv[warp];
    int half = lane & 1;
    int sub = lane >> 1;

    float4 acc = make_float4(0.f, 0.f, 0.f, 0.f);
    for (int j0 = s0; j0 < s1; j0 += 32) {
        int myidx = (j0 + lane < s1) ? __ldg(&g_csr[j0 + lane]) : 0;
        int m = min(32, s1 - j0);
#pragma unroll
        for (int base = 0; base < 32; base += 16) {
            if (base >= m) break;
            int e = base + sub;
            int s = __shfl_sync(FULLMASK, myidx, e);
            if (e < m) {
                float4 v = __ldg((const float4*)(g_xs + (size_t)s * 8) + half);
                acc.x += v.x; acc.y += v.y; acc.z += v.z; acc.w += v.w;
            }
        }
    }
#pragma unroll
    for (int off = 2; off < 32; off <<= 1) {
        acc.x += __shfl_down_sync(FULLMASK, acc.x, off);
        acc.y += __shfl_down_sync(FULLMASK, acc.y, off);
        acc.z += __shfl_down_sync(FULLMASK, acc.z, off);
        acc.w += __shfl_down_sync(FULLMASK, acc.w, off);
    }
    if (lane < 2) {
        float4 self = __ldg((const float4*)(g_xs + (size_t)warp * 8) + lane);
        acc.x = (acc.x + self.x) * dv;
        acc.y = (acc.y + self.y) * dv;
        acc.z = (acc.z + self.z) * dv;
        acc.w = (acc.w + self.w) * dv;
    }
    float xa[8];
    xa[0] = __shfl_sync(FULLMASK, acc.x, 0);
    xa[1] = __shfl_sync(FULLMASK, acc.y, 0);
    xa[2] = __shfl_sync(FULLMASK, acc.z, 0);
    xa[3] = __shfl_sync(FULLMASK, acc.w, 0);
    xa[4] = __shfl_sync(FULLMASK, acc.x, 1);
    xa[5] = __shfl_sync(FULLMASK, acc.y, 1);
    xa[6] = __shfl_sync(FULLMASK, acc.z, 1);
    xa[7] = __shfl_sync(FULLMASK, acc.w, 1);

    float4 r = make_float4(0.f, 0.f, 0.f, 0.f);
#pragma unroll
    for (int k = 0; k < 8; k++) {
        float4 w = ((const float4*)(sW + k * 128))[lane];
        r.x += xa[k] * w.x; r.y += xa[k] * w.y;
        r.z += xa[k] * w.z; r.w += xa[k] * w.w;
    }
    float4 gm = __ldg((const float4*)gamma + lane);
    float4 vr = __ldg((const float4*)var + lane);
    float4 bi = __ldg((const float4*)b0 + lane);
    float4 mn = __ldg((const float4*)mean + lane);
    float4 bt = __ldg((const float4*)beta + lane);
    float rv[4] = {r.x, r.y, r.z, r.w};
    float gmv[4] = {gm.x, gm.y, gm.z, gm.w};
    float vrv[4] = {vr.x, vr.y, vr.z, vr.w};
    float biv[4] = {bi.x, bi.y, bi.z, bi.w};
    float mnv[4] = {mn.x, mn.y, mn.z, mn.w};
    float btv[4] = {bt.x, bt.y, bt.z, bt.w};
    float out[4];
#pragma unroll
    for (int j = 0; j < 4; j++) {
        float scale = gmv[j] * rsqrtf(vrv[j] + BN_EPS);
        float v = rv[j] + biv[j];
        v = (v - mnv[j]) * scale + btv[j];
        out[j] = fmaxf(v, 0.f);
    }
    ((float4*)(g_h + (size_t)warp * HID))[lane] =
        make_float4(out[0], out[1], out[2], out[3]);
}

// ---- 128x128 GEMM: g_h @ W, scaled by dinv, f32x2; bf16 output to g_hls ----
__global__ __launch_bounds__(256, 2) void k_gemm128(const float* __restrict__ W, int n) {
    __shared__ float sW[32][128];
    __shared__ float sA[32][132];   // 16B-aligned rows for LDS.128

    const float* __restrict__ A = g_h;

    int row0 = blockIdx.x * 128;
    int tid = threadIdx.x;
    int lane = tid & 31, warp = tid >> 5;

    ull acc2[8][4];
#pragma unroll
    for (int p = 0; p < 8; p++)
#pragma unroll
        for (int j = 0; j < 4; j++) acc2[p][j] = 0ull;

    for (int kt = 0; kt < 128; kt += 32) {
        const float4* Wv = (const float4*)(W + kt * 128);
        float4* sWv = (float4*)(&sW[0][0]);
#pragma unroll
        for (int i = 0; i < 4; i++) sWv[tid + 256 * i] = Wv[tid + 256 * i];
#pragma unroll
        for (int i = 0; i < 4; i++) {
            int idx = tid + 256 * i;
            int r = idx >> 3, c = idx & 7;
            int row = row0 + r;
            float4 v = make_float4(0.f, 0.f, 0.f, 0.f);
            if (row < n) v = ((const float4*)(A + (size_t)row * 128 + kt))[c];
            sA[c * 4 + 0][r] = v.x; sA[c * 4 + 1][r] = v.y;
            sA[c * 4 + 2][r] = v.z; sA[c * 4 + 3][r] = v.w;
        }
        __syncthreads();
#pragma unroll 8
        for (int k = 0; k < 32; k++) {
            float4 b = ((const float4*)(&sW[k][0]))[lane];
            ull bb0 = pk2(b.x, b.x), bb1 = pk2(b.y, b.y);
            ull bb2 = pk2(b.z, b.z), bb3 = pk2(b.w, b.w);
            const ull* ap = (const ull*)(&sA[k][warp * 16]);
#pragma unroll
            for (int p = 0; p < 8; p++) {
                ull a = ap[p];
                acc2[p][0] = ffma2(a, bb0, acc2[p][0]);
                acc2[p][1] = ffma2(a, bb1, acc2[p][1]);
                acc2[p][2] = ffma2(a, bb2, acc2[p][2]);
                acc2[p][3] = ffma2(a, bb3, acc2[p][3]);
            }
        }
        __syncthreads();
    }
#pragma unroll
    for (int p = 0; p < 8; p++) {
        float lo[4], hi[4];
#pragma unroll
        for (int j = 0; j < 4; j++) upk2(acc2[p][j], lo[j], hi[j]);
        int r0 = row0 + warp * 16 + 2 * p;
        int r1 = r0 + 1;
        if (r0 < n) {
            float dv = g_dinv[r0];
            uint p0 = bfpack(lo[0] * dv, lo[1] * dv);
            uint p1 = bfpack(lo[2] * dv, lo[3] * dv);
            ((uint2*)(g_hls + (size_t)r0 * HID))[lane] = make_uint2(p0, p1);
        }
        if (r1 < n) {
            float dv = g_dinv[r1];
            uint p0 = bfpack(hi[0] * dv, hi[1] * dv);
            uint p1 = bfpack(hi[2] * dv, hi[3] * dv);
            ((uint2*)(g_hls + (size_t)r1 * HID))[lane] = make_uint2(p0, p1);
        }
    }
}

// ------- fused gather-aggregate + BN + ReLU; bf16 gather, fp32 accumulate -------
// one warp per dst node; lane covers 4 columns (uint2 = 4 bf16).
// POOL=0: write g_h. POOL=1: red.add results into g_sums[batch[node]] (no g_h).
template <int POOL>
__global__ void k_aggregate(const float* __restrict__ b, const float* __restrict__ gamma,
                            const float* __restrict__ beta, const float* __restrict__ mean,
                            const float* __restrict__ var,
                            const int* __restrict__ batch, int n) {
    int warp = (blockIdx.x * blockDim.x + threadIdx.x) >> 5;
    int lane = threadIdx.x & 31;
    if (warp >= n) return;

    int s0 = g_rowstart[warp];
    int s1 = g_rowstart[warp + 1];

    // self term
    uint2 sv = __ldg((const uint2*)(g_hls + (size_t)warp * HID) + lane);
    ull acc0 = bf2f2(sv.x), acc1 = bf2f2(sv.y);

    for (int j0 = s0; j0 < s1; j0 += 32) {
        int myidx = (j0 + lane < s1) ? __ldg(&g_csr[j0 + lane]) : 0;
        int m = min(32, s1 - j0);
        int j = 0;
        for (; j + 8 <= m; j += 8) {
            int ia[8];
#pragma unroll
            for (int q = 0; q < 8; q++) ia[q] = __shfl_sync(FULLMASK, myidx, j + q);
            uint2 v[8];
#pragma unroll
            for (int q = 0; q < 8; q++)
                v[q] = __ldg((const uint2*)(g_hls + (size_t)ia[q] * HID) + lane);
#pragma unroll
            for (int q = 0; q < 8; q++) {
                acc0 = fadd2(acc0, bf2f2(v[q].x));
                acc1 = fadd2(acc1, bf2f2(v[q].y));
            }
        }
        for (; j + 4 <= m; j += 4) {
            int i0 = __shfl_sync(FULLMASK, myidx, j);
            int i1 = __shfl_sync(FULLMASK, myidx, j + 1);
            int i2 = __shfl_sync(FULLMASK, myidx, j + 2);
            int i3 = __shfl_sync(FULLMASK, myidx, j + 3);
            uint2 v0 = __ldg((const uint2*)(g_hls + (size_t)i0 * HID) + lane);
            uint2 v1 = __ldg((const uint2*)(g_hls + (size_t)i1 * HID) + lane);
            uint2 v2 = __ldg((const uint2*)(g_hls + (size_t)i2 * HID) + lane);
            uint2 v3 = __ldg((const uint2*)(g_hls + (size_t)i3 * HID) + lane);
            acc0 = fadd2(acc0, fadd2(bf2f2(v0.x), bf2f2(v1.x)));
            acc1 = fadd2(acc1, fadd2(bf2f2(v0.y), bf2f2(v1.y)));
            acc0 = fadd2(acc0, fadd2(bf2f2(v2.x), bf2f2(v3.x)));
            acc1 = fadd2(acc1, fadd2(bf2f2(v2.y), bf2f2(v3.y)));
        }
        for (; j < m; j++) {
            int s = __shfl_sync(FULLMASK, myidx, j);
            uint2 v = __ldg((const uint2*)(g_hls + (size_t)s * HID) + lane);
            acc0 = fadd2(acc0, bf2f2(v.x));
            acc1 = fadd2(acc1, bf2f2(v.y));
        }
    }

    float dv = g_dinv[warp];
    float av[4];
    upk2(acc0, av[0], av[1]);
    upk2(acc1, av[2], av[3]);
    float4 gm = __ldg((const float4*)(gamma) + lane);
    float4 vr = __ldg((const float4*)(var) + lane);
    float4 bi = __ldg((const float4*)(b) + lane);
    float4 mn = __ldg((const float4*)(mean) + lane);
    float4 bt = __ldg((const float4*)(beta) + lane);
    float gmv[4] = {gm.x, gm.y, gm.z, gm.w};
    float vrv[4] = {vr.x, vr.y, vr.z, vr.w};
    float biv[4] = {bi.x, bi.y, bi.z, bi.w};
    float mnv[4] = {mn.x, mn.y, mn.z, mn.w};
    float btv[4] = {bt.x, bt.y, bt.z, bt.w};
    float out[4];
#pragma unroll
    for (int j = 0; j < 4; j++) {
        float scale = gmv[j] * rsqrtf(vrv[j] + BN_EPS);
        float v = av[j] * dv + biv[j];
        v = (v - mnv[j]) * scale + btv[j];
        out[j] = fmaxf(v, 0.f);
    }
    if (POOL) {
        int g = __ldg(batch + warp);
        float* p = g_sums + g * HID + lane * 4;
        asm volatile("red.global.add.v4.f32 [%0], {%1, %2, %3, %4};"
                     :: "l"(p), "f"(out[0]), "f"(out[1]), "f"(out[2]), "f"(out[3])
                     : "memory");
    } else {
        ((float4*)(g_h + (size_t)warp * HID))[lane] =
            make_float4(out[0], out[1], out[2], out[3]);
    }
}

// ------- classifier (pocket MLP fused): per-graph block, 192 -> 96 -> 1 -------
__global__ void k_classify(const float* __restrict__ pocket,
                           const float* __restrict__ pw1, const float* __restrict__ pb1,
                           const float* __restrict__ pw2, const float* __restrict__ pb2,
                           const float* __restrict__ cw1, const float* __restrict__ cb1,
                           const float* __restrict__ cw2, const float* __restrict__ cb2,
                           float* __restrict__ out) {
    __shared__ float p1[64];
    __shared__ float emb[192];
    __shared__ float hid[96];
    int g = blockIdx.x;
    int t = threadIdx.x;  // 192 threads
    if (t < 64) {
        float a = pb1[t];
        for (int k = 0; k < 28; k++) a += pocket[k] * pw1[k * 64 + t];
        p1[t] = fmaxf(a, 0.f);
    }
    if (t < 128) {
        float cnt = fmaxf(g_cnts[g], 1.f);
        emb[t] = g_sums[g * HID + t] / cnt;
    }
    __syncthreads();
    if (t >= 128) {
        int c = t - 128;
        float b = pb2[c];
        for (int k = 0; k < 64; k++) b += p1[k] * pw2[k * 64 + c];
        emb[t] = b;
    }
    __syncthreads();
    if (t < 96) {
        float a = cb1[t];
#pragma unroll 4
        for (int c = 0; c < 192; c++) a += emb[c] * cw1[c * 96 + t];
        hid[t] = fmaxf(a, 0.f);
    }
    __syncthreads();
    if (t == 0) {
        float o = cb2[0];
        for (int j = 0; j < 96; j++) o += hid[j] * cw2[j];
        out[g] = o;
    }
}

// ---------------- launch ----------------
extern "C" void kernel_launch(void* const* d_in, const int* in_sizes, int n_in,
                              void* d_out, int out_size) {
    const float* x      = (const float*)d_in[0];
    const int*   ei     = (const int*)  d_in[1];
    const int*   batch  = (const int*)  d_in[2];
    const float* pocket = (const float*)d_in[3];
    const float* W0 = (const float*)d_in[4];
    const float* b0 = (const float*)d_in[5];
    const float* W1 = (const float*)d_in[6];
    const float* b1 = (const float*)d_in[7];
    const float* W2 = (const float*)d_in[8];
    const float* b2 = (const float*)d_in[9];
    const float* bn_gamma = (const float*)d_in[10];
    const float* bn_beta  = (const float*)d_in[11];
    const float* bn_mean  = (const float*)d_in[12];
    const float* bn_var   = (const float*)d_in[13];
    const float* pw1 = (const float*)d_in[14];
    const float* pb1 = (const float*)d_in[15];
    const float* pw2 = (const float*)d_in[16];
    const float* pb2 = (const float*)d_in[17];
    const float* cw1 = (const float*)d_in[18];
    const float* cb1 = (const float*)d_in[19];
    const float* cw2 = (const float*)d_in[20];
    const float* cb2 = (const float*)d_in[21];
    float* out = (float*)d_out;

    int n = in_sizes[0] / 7;       // 100000
    int e = in_sizes[1] / 2;       // 600000
    const int* src = ei;
    const int* dst = ei + e;

    int L = n + 1;
    int NB = (L + 1023) / 1024;    // 98

    // CSR build (by dst); scan1 fuses dinv + xs-prep + pool-zero; scan3 counts
    k_zero_rs<<<(L + 255) / 256, 256>>>(L);
    k_hist<<<(e + 255) / 256, 256>>>(dst, e);
    k_scan1<<<NB, 256>>>(x, L, n);
    k_scan2<<<1, 128>>>(NB);
    k_scan3<<<NB, 256>>>(batch, L, n);
    k_fill<<<(e + 255) / 256, 256>>>(src, dst, e);

    int agg_blocks = (n * 32 + 255) / 256;

    // layer 0: fused aggregate(8-dim) + GEMM + BN + ReLU
    k_layer0<<<agg_blocks, 256>>>(W0, b0, bn_gamma, bn_beta, bn_mean, bn_var, n);
    // layer 1
    k_gemm128<<<(n + 127) / 128, 256>>>(W1, n);
    k_aggregate<0><<<agg_blocks, 256>>>(b1, bn_gamma + HID, bn_beta + HID,
                                        bn_mean + HID, bn_var + HID, batch, n);
    // layer 2 (aggregate pools directly into g_sums)
    k_gemm128<<<(n + 127) / 128, 256>>>(W2, n);
    k_aggregate<1><<<agg_blocks, 256>>>(b2, bn_gamma + 2 * HID, bn_beta + 2 * HID,
                                        bn_mean + 2 * HID, bn_var + 2 * HID, batch, n);

    // classifier (pocket fused)
    k_classify<<<NG, 192>>>(pocket, pw1, pb1, pw2, pb2,
                            cw1, cb1, cw2, cb2, out);
}